// round 1
// baseline (speedup 1.0000x reference)
#include <cuda_runtime.h>

#define D 128
#define NG 64
#define CO 16
#define MAXN 50176
#define NEG 0.1f

// -------- scratch (device globals: allocation-free workaround) --------
__device__ float g_h1[MAXN * D];
__device__ float g_h2[MAXN * D];
__device__ float g_agg[MAXN * D];
__device__ float g_deg[MAXN];
__device__ float g_dinv[MAXN];
__device__ float g_pool[NG * D];
__device__ float g_cnt[NG];

__device__ __forceinline__ float lrelu(float v) {
    return v >= 0.0f ? v : NEG * v;
}

// -------- init: zero agg/pool/cnt, deg = 1 (self-loop) --------
__global__ void k_init(int n) {
    int stride = gridDim.x * blockDim.x;
    int i0 = blockIdx.x * blockDim.x + threadIdx.x;
    int tot = n * D;
    for (int i = i0; i < tot; i += stride) g_agg[i] = 0.0f;
    for (int i = i0; i < n; i += stride) g_deg[i] = 1.0f;
    for (int i = i0; i < NG * D; i += stride) g_pool[i] = 0.0f;
    for (int i = i0; i < NG; i += stride) g_cnt[i] = 0.0f;
}

__global__ void k_zero_agg(int n) {
    int stride = gridDim.x * blockDim.x;
    int tot = n * D;
    for (int i = blockIdx.x * blockDim.x + threadIdx.x; i < tot; i += stride)
        g_agg[i] = 0.0f;
}

// -------- degree over dst --------
__global__ void k_deg(const int* __restrict__ dst, int E) {
    int stride = gridDim.x * blockDim.x;
    for (int e = blockIdx.x * blockDim.x + threadIdx.x; e < E; e += stride)
        atomicAdd(&g_deg[dst[e]], 1.0f);
}

__global__ void k_dinv(int n) {
    int i = blockIdx.x * blockDim.x + threadIdx.x;
    if (i < n) g_dinv[i] = rsqrtf(g_deg[i]);
}

// -------- GEMM: out[n,128] = A[n,128] @ W[128,128] --------
// 128 threads/block. W cached in dynamic SMEM (64KB), 16 rows of A staged
// per iteration (8KB). Each thread: 4 cols (lane*4) x 4 rows -> 16 accums.
__global__ void k_gemm(const float* __restrict__ A, const float* __restrict__ W,
                       float* __restrict__ out, int n) {
    extern __shared__ float sm[];
    float* Ws = sm;            // 128*128
    float* xs = sm + D * D;    // 16*128
    int t = threadIdx.x;
    for (int i = t; i < (D * D) / 4; i += 128)
        ((float4*)Ws)[i] = ((const float4*)W)[i];
    __syncthreads();

    int lane = t & 31;
    int wg = t >> 5;
    int col = lane * 4;
    int rb = wg * 4;

    for (int r0 = blockIdx.x * 16; r0 < n; r0 += gridDim.x * 16) {
        int rows = n - r0;
        if (rows > 16) rows = 16;
        __syncthreads();  // previous tile's consumers done with xs
        for (int i = t; i < rows * (D / 4); i += 128)
            ((float4*)xs)[i] = ((const float4*)(A + (size_t)r0 * D))[i];
        __syncthreads();

        float4 a0 = {0,0,0,0}, a1 = {0,0,0,0}, a2 = {0,0,0,0}, a3 = {0,0,0,0};
        #pragma unroll 4
        for (int k = 0; k < D; k++) {
            float4 w = *(const float4*)&Ws[k * D + col];
            float x0 = xs[(rb + 0) * D + k];
            float x1 = xs[(rb + 1) * D + k];
            float x2 = xs[(rb + 2) * D + k];
            float x3 = xs[(rb + 3) * D + k];
            a0.x += x0 * w.x; a0.y += x0 * w.y; a0.z += x0 * w.z; a0.w += x0 * w.w;
            a1.x += x1 * w.x; a1.y += x1 * w.y; a1.z += x1 * w.z; a1.w += x1 * w.w;
            a2.x += x2 * w.x; a2.y += x2 * w.y; a2.z += x2 * w.z; a2.w += x2 * w.w;
            a3.x += x3 * w.x; a3.y += x3 * w.y; a3.z += x3 * w.z; a3.w += x3 * w.w;
        }
        if (rb + 0 < rows) *(float4*)&out[(size_t)(r0 + rb + 0) * D + col] = a0;
        if (rb + 1 < rows) *(float4*)&out[(size_t)(r0 + rb + 1) * D + col] = a1;
        if (rb + 2 < rows) *(float4*)&out[(size_t)(r0 + rb + 2) * D + col] = a2;
        if (rb + 3 < rows) *(float4*)&out[(size_t)(r0 + rb + 3) * D + col] = a3;
    }
}

// -------- edge scatter: agg[dst] += coef * h[src], warp per edge --------
__global__ void k_scatter(const float* __restrict__ h, const int* __restrict__ src,
                          const int* __restrict__ dst, int E) {
    int e = blockIdx.x * 8 + (threadIdx.x >> 5);
    if (e >= E) return;
    int lane = threadIdx.x & 31;
    int s = src[e], d = dst[e];
    float coef = g_dinv[s] * g_dinv[d];
    float4 v = ((const float4*)(h + (size_t)s * D))[lane];
    float4 w = make_float4(v.x * coef, v.y * coef, v.z * coef, v.w * coef);
    atomicAdd(((float4*)(g_agg + (size_t)d * D)) + lane, w);
}

// -------- combine: h = leaky(agg + h*dinv^2 + b), in place --------
__global__ void k_combine(float* __restrict__ h, const float* __restrict__ bias, int n) {
    int stride = gridDim.x * blockDim.x;
    int tot = n * (D / 4);
    const float4* agg4 = (const float4*)g_agg;
    float4* h4 = (float4*)h;
    const float4* b4 = (const float4*)bias;
    for (int i = blockIdx.x * blockDim.x + threadIdx.x; i < tot; i += stride) {
        int node = i >> 5;
        int f4 = i & 31;
        float di = g_dinv[node];
        float d2 = di * di;
        float4 a = agg4[i], hv = h4[i], b = b4[f4];
        float4 r;
        r.x = lrelu(a.x + hv.x * d2 + b.x);
        r.y = lrelu(a.y + hv.y * d2 + b.y);
        r.z = lrelu(a.z + hv.z * d2 + b.z);
        r.w = lrelu(a.w + hv.w * d2 + b.w);
        h4[i] = r;
    }
}

// -------- layer-2 combine + global mean pool (sum + count via atomics) --------
__global__ void k_pool(const float* __restrict__ h, const float* __restrict__ bias,
                       const int* __restrict__ batch, int n) {
    int node = blockIdx.x * 8 + (threadIdx.x >> 5);
    if (node >= n) return;
    int lane = threadIdx.x & 31;
    float di = g_dinv[node];
    float d2 = di * di;
    float4 a = ((const float4*)g_agg)[node * 32 + lane];
    float4 hv = ((const float4*)h)[node * 32 + lane];
    float4 b = ((const float4*)bias)[lane];
    float4 v;
    v.x = lrelu(a.x + hv.x * d2 + b.x);
    v.y = lrelu(a.y + hv.y * d2 + b.y);
    v.z = lrelu(a.z + hv.z * d2 + b.z);
    v.w = lrelu(a.w + hv.w * d2 + b.w);
    int gid = batch[node];
    atomicAdd(((float4*)g_pool) + gid * 32 + lane, v);
    if (lane == 0) atomicAdd(&g_cnt[gid], 1.0f);
}

// -------- head: out[g,c] = (pool[g]/cnt[g]) @ Wl + bl --------
__global__ void k_final(const float* __restrict__ Wl, const float* __restrict__ bl,
                        float* __restrict__ out) {
    int t = threadIdx.x;           // 1024 threads, 1 block
    int g = t >> 4;
    int c = t & 15;
    float cnt = fmaxf(g_cnt[g], 1.0f);
    float s = 0.0f;
    #pragma unroll 8
    for (int f = 0; f < D; f++)
        s += g_pool[g * D + f] * Wl[f * CO + c];
    out[g * CO + c] = s / cnt + bl[c];
}

extern "C" void kernel_launch(void* const* d_in, const int* in_sizes, int n_in,
                              void* d_out, int out_size) {
    const float* x     = (const float*)d_in[0];
    const int*   ei    = (const int*)d_in[1];
    const int*   batch = (const int*)d_in[2];
    const float* W1    = (const float*)d_in[3];
    const float* b1    = (const float*)d_in[4];
    const float* W2    = (const float*)d_in[5];
    const float* b2    = (const float*)d_in[6];
    const float* Wl    = (const float*)d_in[7];
    const float* bl    = (const float*)d_in[8];

    int n = in_sizes[0] / D;
    int E = in_sizes[1] / 2;
    const int* src = ei;
    const int* dst = ei + E;

    void *ph1 = nullptr, *ph2 = nullptr;
    cudaGetSymbolAddress(&ph1, g_h1);
    cudaGetSymbolAddress(&ph2, g_h2);
    float* h1 = (float*)ph1;
    float* h2 = (float*)ph2;

    int smem = (D * D + 16 * D) * (int)sizeof(float);  // 73728 B
    cudaFuncSetAttribute(k_gemm, cudaFuncAttributeMaxDynamicSharedMemorySize, smem);

    int eblocks = (E + 7) / 8;

    k_init<<<4096, 256>>>(n);
    k_deg<<<2048, 256>>>(dst, E);
    k_dinv<<<(n + 255) / 256, 256>>>(n);

    // Layer 1
    k_gemm<<<444, 128, smem>>>(x, W1, h1, n);
    k_scatter<<<eblocks, 256>>>(h1, src, dst, E);
    k_combine<<<2048, 256>>>(h1, b1, n);

    // Layer 2
    k_zero_agg<<<4096, 256>>>(n);
    k_gemm<<<444, 128, smem>>>(h1, W2, h2, n);
    k_scatter<<<eblocks, 256>>>(h2, src, dst, E);
    k_pool<<<(n + 7) / 8, 256>>>(h2, b2, batch, n);

    // Head
    k_final<<<1, 1024>>>(Wl, bl, (float*)d_out);
}